// round 6
// baseline (speedup 1.0000x reference)
#include <cuda_runtime.h>

// LFQ quantizer — sparse factorized softmax, single kernel, NO spin barrier.
// N = 8192 samples, D = 14 dims, K = 16384 codes, T = 0.01.
//
// softmax factorizes: p_j = prod_d sigmoid(400 x_d c_jd).
// u_d = e^{-400|x_d|} > 1e-8 only for |x_d| < 0.046 (~3.7% of dims), so each
// sample's probability mass lives on ~1.7 codes: enumerate subsets of the
// soft-dim mask, scatter ~14K atomics total into g_M.
// sample_entropy = sum_d binary_entropy(sigmoid(400 x_d))  (exact, factorized).
//
// Structure: 32 blocks x 256 threads (1 thread/sample). Phase 1 scatters and
// writes per-block partials to distinct slots. Each block then takes a ticket;
// all but the last EXIT. The last-arriving block alone reduces the 16K-code
// entropy, re-zeros g_M, assembles the 4 scalars, and resets the ticket
// (graph-replay safe).

#define DIMS 14
#define NCODES 16384
#define NB 32
#define BTH 256
#define UTH 1e-8f

__device__ float g_M[NCODES];          // sum of probs per code (zeroed each run)
__device__ float g_cP[NB], g_hP[NB];   // per-block commit / sample-entropy partials
__device__ unsigned int g_ticket;

__global__ __launch_bounds__(BTH) void lfq_fused(const float* __restrict__ x,
                                                 float* __restrict__ out,
                                                 int qn, int out_size,
                                                 float inv_n) {
    __shared__ float wsum[8], wsum2[8];
    __shared__ int s_last;

    const int tid = threadIdx.x;
    const int gid = blockIdx.x * BTH + tid;      // sample id
    const int lane = tid & 31, wid = tid >> 5;

    // ================= phase 1: per-sample =================
    float u_loc[DIMS];
    float commit_acc = 0.f, h_acc = 0.f;
    float p_main = 1.f;
    int j_main = 0;
    unsigned soft = 0;

    const float* xp = x + gid * DIMS;
    float* op = out + gid * DIMS;

    #pragma unroll
    for (int d = 0; d < DIMS; ++d) {
        float xv = xp[d];
        float qz = (xv > 0.f) ? 1.f : -1.f;
        op[d] = qz;
        float dq = xv - qz;
        commit_acc += dq * dq;

        float t = fabsf(400.f * xv);
        float u = __expf(-t);                    // flip ratio e^{-|z|}
        if (xv > 0.f) j_main |= (1 << d);

        if (u > 1e-4f) {                         // soft-ish: exact formulas
            float inv = 1.f / (1.f + u);
            h_acc += log1pf(u) + t * u * inv;    // stable binary entropy
            p_main *= inv;
        } else {                                 // hard: 1st order, err ~ u^2
            h_acc += u * (1.f + t);
            p_main *= (1.f - u);
        }
        u_loc[d] = u;
        if (u > UTH) soft |= (1u << d);
    }

    // enumerate all subsets of `soft` (incl. empty), scatter to g_M
    unsigned m = 0;
    do {
        float p = p_main;
        unsigned r = m;
        while (r) {
            int d = __ffs(r) - 1;
            p *= u_loc[d];
            r &= r - 1;
        }
        atomicAdd(&g_M[j_main ^ (int)m], p);
        m = (m - soft) & soft;                   // next subset of `soft`
    } while (m);

    // block-reduce commit & sample-entropy partials -> distinct slots
    #pragma unroll
    for (int off = 16; off; off >>= 1) {
        commit_acc += __shfl_down_sync(0xffffffffu, commit_acc, off);
        h_acc      += __shfl_down_sync(0xffffffffu, h_acc, off);
    }
    if (lane == 0) { wsum[wid] = commit_acc; wsum2[wid] = h_acc; }

    // ---- release: make this block's g_M atomics + partials visible ----
    __threadfence();
    __syncthreads();
    if (tid == 0) {
        float cs = 0.f, hs = 0.f;
        #pragma unroll
        for (int w = 0; w < 8; ++w) { cs += wsum[w]; hs += wsum2[w]; }
        g_cP[blockIdx.x] = cs;
        g_hP[blockIdx.x] = hs;
        __threadfence();
        unsigned tk = atomicAdd(&g_ticket, 1u);
        s_last = (tk == NB - 1);
    }
    __syncthreads();
    if (!s_last) return;                         // 31 blocks exit immediately

    // ================= last block: finalize =================
    __threadfence();                             // acquire side
    float ea = 0.f;
    #pragma unroll 4
    for (int c = tid; c < NCODES; c += BTH) {
        float v = __ldcg(&g_M[c]);
        if (v != 0.f) {
            float mm = v * inv_n;
            ea -= mm * __logf(mm + 1e-5f);
            g_M[c] = 0.f;                        // reset for next graph replay
        }
    }
    #pragma unroll
    for (int off = 16; off; off >>= 1)
        ea += __shfl_down_sync(0xffffffffu, ea, off);
    if (lane == 0) wsum[wid] = ea;
    __syncthreads();

    if (wid == 0) {                              // warp 0: sum partial slots
        float cs = (lane < NB) ? g_cP[lane] : 0.f;
        float hs = (lane < NB) ? g_hP[lane] : 0.f;
        #pragma unroll
        for (int off = 16; off; off >>= 1) {
            cs += __shfl_down_sync(0xffffffffu, cs, off);
            hs += __shfl_down_sync(0xffffffffu, hs, off);
        }
        if (lane == 0) {
            float avg = 0.f;
            #pragma unroll
            for (int w = 0; w < 8; ++w) avg += wsum[w];
            float samp = hs * inv_n;
            float cm = cs * inv_n * (1.f / (float)DIMS);
            if (out_size >= qn + 4) {
                out[qn + 0] = samp - avg;        // entropy_aux_loss
                out[qn + 1] = samp;              // sample_entropy
                out[qn + 2] = avg;               // avg_entropy
                out[qn + 3] = cm;                // commit_loss
            }
            g_ticket = 0u;                       // reset for next replay
        }
    }
}

extern "C" void kernel_launch(void* const* d_in, const int* in_sizes, int n_in,
                              void* d_out, int out_size) {
    const float* x = (const float*)d_in[0];
    float* out = (float*)d_out;
    int qn = in_sizes[0];                  // 8*1024*14 = 114688
    float inv_n = 1.f / (float)(qn / DIMS);

    lfq_fused<<<NB, BTH>>>(x, out, qn, out_size, inv_n);
}

// round 7
// speedup vs baseline: 1.5588x; 1.5588x over previous
#include <cuda_runtime.h>

// LFQ quantizer — sparse factorized softmax, single kernel, coalesced phase 1,
// spin barrier + distributed phase 2 (round-5 structure, optimized).
// N = 8192 samples, D = 14, K = 16384, T = 0.01.
//
// p_j = prod_d sigmoid(400 x_d c_jd); u_d = e^{-400|x_d|} > 1e-8 only for
// |x_d| < 0.046, so each sample's mass lives on ~1.7 codes -> subset scatter.
// sample_entropy = sum_d binary_entropy(sigmoid(400 x_d)) (factorized, exact).

#define DIMS 14
#define NCODES 16384
#define NB 128
#define BTH 64
#define SPB 64                 // samples per block
#define EPB (SPB * DIMS)       // 896 floats per block
#define E4PB (EPB / 4)         // 224 float4
#define CPB (NCODES / NB)      // 128 codes per block in phase 2
#define UTH 1e-8f

__device__ float g_M[NCODES];                 // per-code prob sums (zeroed each run)
__device__ float g_sC, g_sH, g_sE;            // commit / sampleH / avgH accumulators
__device__ unsigned g_bar, g_go, g_ticket;

__global__ __launch_bounds__(BTH) void lfq_fused(const float* __restrict__ x,
                                                 float* __restrict__ out,
                                                 int qn, int out_size,
                                                 float inv_n) {
    __shared__ unsigned us[EPB];   // bit31 = quantized bit, bits30..0 = u (exact)
    __shared__ float w1[2], w2[2];

    const int tid = threadIdx.x;
    const int lane = tid & 31, wid = tid >> 5;
    const float4* x4 = (const float4*)x + blockIdx.x * E4PB;
    float4* o4 = (float4*)out + blockIdx.x * E4PB;

    // ========== phase 1a: elementwise, fully coalesced float4 ==========
    float commit = 0.f, h = 0.f;
    #pragma unroll
    for (int k = 0; k < 4; ++k) {
        int i = tid + k * BTH;
        if (i < E4PB) {
            float4 xv = x4[i];
            float vx[4] = {xv.x, xv.y, xv.z, xv.w};
            float qq[4];
            #pragma unroll
            for (int j = 0; j < 4; ++j) {
                float v = vx[j];
                bool pos = (v > 0.f);
                float qz = pos ? 1.f : -1.f;
                qq[j] = qz;
                float dq = v - qz;
                commit += dq * dq;
                float t = fabsf(400.f * v);
                float u = __expf(-t);                    // flip ratio e^{-|z|}
                float inv = 1.f / (1.f + u);
                h += (u > 1e-4f) ? (__logf(1.f + u) + t * u * inv)
                                 : u * (1.f + t);        // 1st order, err ~ u^2
                us[4 * i + j] = __float_as_uint(u) | (pos ? 0x80000000u : 0u);
            }
            float4 q; q.x = qq[0]; q.y = qq[1]; q.z = qq[2]; q.w = qq[3];
            o4[i] = q;                                   // coalesced STG.128
        }
    }
    __syncthreads();

    // ========== phase 1b: per-sample sparse scatter ==========
    {
        const unsigned* up = &us[tid * DIMS];
        float p_main = 1.f;
        int j_main = 0;
        unsigned soft = 0;
        #pragma unroll
        for (int d = 0; d < DIMS; ++d) {
            unsigned w = up[d];
            float u = __uint_as_float(w & 0x7fffffffu);
            if (w >> 31) j_main |= (1 << d);
            p_main *= 1.f / (1.f + u);
            if (u > UTH) soft |= (1u << d);
        }
        unsigned m = 0;
        do {                                             // subsets of `soft`
            float p = p_main;
            unsigned r = m;
            while (r) {
                int d = __ffs(r) - 1;
                p *= __uint_as_float(up[d] & 0x7fffffffu);
                r &= r - 1;
            }
            atomicAdd(&g_M[j_main ^ (int)m], p);
            m = (m - soft) & soft;
        } while (m);
    }

    // block-reduce commit & sample-entropy (2 warps)
    #pragma unroll
    for (int off = 16; off; off >>= 1) {
        commit += __shfl_down_sync(0xffffffffu, commit, off);
        h      += __shfl_down_sync(0xffffffffu, h, off);
    }
    if (lane == 0) { w1[wid] = commit; w2[wid] = h; }

    // ========== grid barrier: count + release flag ==========
    __threadfence();                    // publish g_M atomics & partials
    __syncthreads();
    if (tid == 0) {
        atomicAdd(&g_sC, w1[0] + w1[1]);
        atomicAdd(&g_sH, w2[0] + w2[1]);
        __threadfence();
        if (atomicAdd(&g_bar, 1u) == NB - 1) atomicExch(&g_go, 1u);
        while (((volatile unsigned*)&g_go)[0] == 0u) {}  // tight poll on one line
    }
    __syncthreads();
    __threadfence();                    // acquire

    // ========== phase 2: distributed entropy over avg_probs + re-zero ==========
    float ea = 0.f;
    const int base = blockIdx.x * CPB;
    #pragma unroll
    for (int k = 0; k < CPB / BTH; ++k) {               // 2 iters, coalesced
        int c = base + k * BTH + tid;
        float v = __ldcg(&g_M[c]);
        g_M[c] = 0.f;                                    // reset for next replay
        if (v != 0.f) {
            float mm = v * inv_n;
            ea -= mm * __logf(mm + 1e-5f);
        }
    }
    #pragma unroll
    for (int off = 16; off; off >>= 1)
        ea += __shfl_down_sync(0xffffffffu, ea, off);
    if (lane == 0) w1[wid] = ea;
    __syncthreads();

    if (tid == 0) {
        atomicAdd(&g_sE, w1[0] + w1[1]);
        __threadfence();
        if (atomicAdd(&g_ticket, 1u) == NB - 1) {        // last block finalizes
            __threadfence();
            float samp = __ldcg(&g_sH) * inv_n;
            float avg  = __ldcg(&g_sE);
            float cm   = __ldcg(&g_sC) * inv_n * (1.f / (float)DIMS);
            if (out_size >= qn + 4) {
                out[qn + 0] = samp - avg;                // entropy_aux_loss
                out[qn + 1] = samp;                      // sample_entropy
                out[qn + 2] = avg;                       // avg_entropy
                out[qn + 3] = cm;                        // commit_loss
            }
            g_sC = 0.f; g_sH = 0.f; g_sE = 0.f;          // reset for next replay
            g_bar = 0u; g_ticket = 0u;
            atomicExch(&g_go, 0u);
        }
    }
}

extern "C" void kernel_launch(void* const* d_in, const int* in_sizes, int n_in,
                              void* d_out, int out_size) {
    const float* x = (const float*)d_in[0];
    float* out = (float*)d_out;
    int qn = in_sizes[0];                   // 8*1024*14 = 114688
    float inv_n = 1.f / (float)(qn / DIMS); // 1/8192

    lfq_fused<<<NB, BTH>>>(x, out, qn, out_size, inv_n);
}